// round 1
// baseline (speedup 1.0000x reference)
#include <cuda_runtime.h>
#include <cstdint>

// Problem constants (fixed by the dataset)
#define NN   100000
#define EMAX 3200000

// ---------------- scratch (device globals; no allocation allowed) ----------
__device__ float    g_h1  [NN * 16];   // layer1 transformed features
__device__ float    g_out1[NN * 16];   // layer1 aggregate -> layer1 output (in place)
__device__ float    g_h2  [NN * 64];   // layer2 transformed features
__device__ float    g_as  [NN];        // alpha_src per node (reused across layers)
__device__ float    g_ad  [NN];        // alpha_dst per node
__device__ unsigned g_menc[NN];        // encoded segment max
__device__ float    g_s   [NN];        // segment sum of p
__device__ float    g_w1a [4];         // W1 @ a_src1 (2), W1 @ a_dst1 (2)
__device__ float    g_w2a [32];        // W2 @ a_src2 (16), W2 @ a_dst2 (16)

// ---------------- helpers ---------------------------------------------------
__device__ __forceinline__ unsigned fenc(float f) {
    unsigned u = __float_as_uint(f);
    return (u & 0x80000000u) ? ~u : (u ^ 0x80000000u);
}
__device__ __forceinline__ float fdec(unsigned u) {
    return __uint_as_float((u & 0x80000000u) ? (u ^ 0x80000000u) : ~u);
}
__device__ __forceinline__ float lrelu(float v) {
    return v > 0.f ? v : 0.2f * v;
}
__device__ __forceinline__ void red_add_v4(float* ptr, float4 v) {
    asm volatile("red.global.add.v4.f32 [%0], {%1,%2,%3,%4};"
                 :: "l"(ptr), "f"(v.x), "f"(v.y), "f"(v.z), "f"(v.w)
                 : "memory");
}

// ---------------- tiny precompute: project attention vectors through W -----
__global__ void k_prep(const float* __restrict__ W1, const float* __restrict__ as1,
                       const float* __restrict__ ad1,
                       const float* __restrict__ W2, const float* __restrict__ as2,
                       const float* __restrict__ ad2) {
    int t = threadIdx.x;
    if (t < 2) {
        float s = 0.f, d = 0.f;
        #pragma unroll
        for (int f = 0; f < 16; f++) {
            s += W1[t * 16 + f] * as1[f];
            d += W1[t * 16 + f] * ad1[f];
        }
        g_w1a[t] = s; g_w1a[2 + t] = d;
    }
    if (t < 16) {
        float s = 0.f, d = 0.f;
        #pragma unroll
        for (int f = 0; f < 64; f++) {
            s += W2[t * 64 + f] * as2[f];
            d += W2[t * 64 + f] * ad2[f];
        }
        g_w2a[t] = s; g_w2a[16 + t] = d;
    }
}

// ---------------- layer 1 node pass: h1 = x@W1, alpha, init, zero agg ------
__global__ void k_l1_node(const float* __restrict__ x, const float* __restrict__ W1, int n) {
    int i = blockIdx.x * blockDim.x + threadIdx.x;
    if (i >= n) return;
    float x0 = x[2 * i], x1 = x[2 * i + 1];
    float4 z = make_float4(0.f, 0.f, 0.f, 0.f);
    #pragma unroll
    for (int g = 0; g < 4; g++) {
        float4 w0 = __ldg(((const float4*)W1) + g);      // row 0
        float4 w1 = __ldg(((const float4*)W1) + 4 + g);  // row 1
        float4 h;
        h.x = x0 * w0.x + x1 * w1.x;
        h.y = x0 * w0.y + x1 * w1.y;
        h.z = x0 * w0.z + x1 * w1.z;
        h.w = x0 * w0.w + x1 * w1.w;
        ((float4*)(g_h1 + i * 16))[g]   = h;
        ((float4*)(g_out1 + i * 16))[g] = z;
    }
    g_as[i]   = x0 * g_w1a[0] + x1 * g_w1a[1];
    g_ad[i]   = x0 * g_w1a[2] + x1 * g_w1a[3];
    g_menc[i] = fenc(-__int_as_float(0x7f800000));  // fenc(-inf)
    g_s[i]    = 0.f;
}

// ---------------- edge pass: segment max over dst ---------------------------
__global__ void k_max(const int* __restrict__ ei, int E, int EE) {
    int e = blockIdx.x * blockDim.x + threadIdx.x;
    if (e >= EE) return;
    int src, dst;
    if (e < E) { src = ei[e]; dst = ei[E + e]; }
    else       { src = dst = e - E; }
    float v = lrelu(g_as[src] + g_ad[dst]);
    atomicMax(&g_menc[dst], fenc(v));
}

// ---------------- layer 1 edge aggregate: 4 lanes/edge (F=16) --------------
__global__ void k_agg1(const int* __restrict__ ei, int E, int EE) {
    int gid  = blockIdx.x * blockDim.x + threadIdx.x;
    int e    = gid >> 2;
    int lane = gid & 3;
    if (e >= EE) return;
    int src, dst;
    if (e < E) { src = ei[e]; dst = ei[E + e]; }
    else       { src = dst = e - E; }
    float v = lrelu(g_as[src] + g_ad[dst]);
    float p = __expf(v - fdec(g_menc[dst]));
    if (lane == 0) atomicAdd(&g_s[dst], p);
    float4 hv = *(const float4*)(g_h1 + src * 16 + lane * 4);
    float4 r  = make_float4(p * hv.x, p * hv.y, p * hv.z, p * hv.w);
    red_add_v4(g_out1 + dst * 16 + lane * 4, r);
}

// ---------------- layer 1 epilogue: out1 = relu(agg/s + b1) (in place) -----
__global__ void k_fin1(const float* __restrict__ b1, int n) {
    int idx = blockIdx.x * blockDim.x + threadIdx.x;  // node*4 float4-groups
    if (idx >= n * 4) return;
    int node = idx >> 2, g = idx & 3;
    float sinv = 1.f / g_s[node];
    float4 a  = ((float4*)g_out1)[idx];
    float4 bb = __ldg(((const float4*)b1) + g);
    a.x = fmaxf(a.x * sinv + bb.x, 0.f);
    a.y = fmaxf(a.y * sinv + bb.y, 0.f);
    a.z = fmaxf(a.z * sinv + bb.z, 0.f);
    a.w = fmaxf(a.w * sinv + bb.w, 0.f);
    ((float4*)g_out1)[idx] = a;
}

// ---------------- layer 2 node pass: h2 = out1@W2, alpha, init --------------
__global__ void k_l2_node(const float* __restrict__ W2, int n) {
    int idx = blockIdx.x * blockDim.x + threadIdx.x;  // node*16 float4-groups
    if (idx >= n * 16) return;
    int node = idx >> 4, g = idx & 15;
    const float* in = g_out1 + node * 16;
    float4 acc = make_float4(0.f, 0.f, 0.f, 0.f);
    #pragma unroll
    for (int k = 0; k < 16; k++) {
        float ik = in[k];
        float4 w = __ldg(((const float4*)W2) + k * 16 + g);
        acc.x += ik * w.x;
        acc.y += ik * w.y;
        acc.z += ik * w.z;
        acc.w += ik * w.w;
    }
    ((float4*)(g_h2 + node * 64))[g] = acc;
    if (g == 0) {
        float s = 0.f, d = 0.f;
        #pragma unroll
        for (int k = 0; k < 16; k++) {
            s += in[k] * g_w2a[k];
            d += in[k] * g_w2a[16 + k];
        }
        g_as[node]   = s;
        g_ad[node]   = d;
        g_menc[node] = fenc(-__int_as_float(0x7f800000));
        g_s[node]    = 0.f;
    }
}

// ---------------- layer 2 edge aggregate: 16 lanes/edge (F=64) --------------
__global__ void k_agg2(const int* __restrict__ ei, int E, int EE, float* __restrict__ out) {
    int gid  = blockIdx.x * blockDim.x + threadIdx.x;
    int e    = gid >> 4;
    int lane = gid & 15;
    if (e >= EE) return;
    int src, dst;
    if (e < E) { src = ei[e]; dst = ei[E + e]; }
    else       { src = dst = e - E; }
    float v = lrelu(g_as[src] + g_ad[dst]);
    float p = __expf(v - fdec(g_menc[dst]));
    if (lane == 0) atomicAdd(&g_s[dst], p);
    float4 hv = *(const float4*)(g_h2 + src * 64 + lane * 4);
    float4 r  = make_float4(p * hv.x, p * hv.y, p * hv.z, p * hv.w);
    red_add_v4(out + dst * 64 + lane * 4, r);
}

// ---------------- layer 2 epilogue: out = relu(out/s + b2) ------------------
__global__ void k_fin2(float* __restrict__ out, const float* __restrict__ b2, int n) {
    int idx = blockIdx.x * blockDim.x + threadIdx.x;  // node*16 float4-groups
    if (idx >= n * 16) return;
    int node = idx >> 4, g = idx & 15;
    float sinv = 1.f / g_s[node];
    float4 a  = ((float4*)out)[idx];
    float4 bb = __ldg(((const float4*)b2) + g);
    a.x = fmaxf(a.x * sinv + bb.x, 0.f);
    a.y = fmaxf(a.y * sinv + bb.y, 0.f);
    a.z = fmaxf(a.z * sinv + bb.z, 0.f);
    a.w = fmaxf(a.w * sinv + bb.w, 0.f);
    ((float4*)out)[idx] = a;
}

// ---------------- launch -----------------------------------------------------
extern "C" void kernel_launch(void* const* d_in, const int* in_sizes, int n_in,
                              void* d_out, int out_size) {
    const float* x   = (const float*)d_in[0];
    const int*   ei  = (const int*)  d_in[1];
    const float* W1  = (const float*)d_in[2];
    const float* as1 = (const float*)d_in[3];
    const float* ad1 = (const float*)d_in[4];
    const float* b1  = (const float*)d_in[5];
    const float* W2  = (const float*)d_in[6];
    const float* as2 = (const float*)d_in[7];
    const float* ad2 = (const float*)d_in[8];
    const float* b2  = (const float*)d_in[9];
    float* out = (float*)d_out;

    int n  = in_sizes[0] / 2;   // N = 100000
    int E  = in_sizes[1] / 2;   // 3.2M
    int EE = E + n;             // with self-loops

    const int T = 256;

    k_prep<<<1, 64>>>(W1, as1, ad1, W2, as2, ad2);

    // ---- layer 1 ----
    k_l1_node<<<(n + T - 1) / T, T>>>(x, W1, n);
    k_max<<<(EE + T - 1) / T, T>>>(ei, E, EE);
    k_agg1<<<(EE * 4 + T - 1) / T, T>>>(ei, E, EE);
    k_fin1<<<(n * 4 + T - 1) / T, T>>>(b1, n);

    // ---- layer 2 ----
    k_l2_node<<<(n * 16 + T - 1) / T, T>>>(W2, n);
    k_max<<<(EE + T - 1) / T, T>>>(ei, E, EE);
    cudaMemsetAsync(out, 0, (size_t)out_size * sizeof(float), 0);
    k_agg2<<<(EE * 16 + T - 1) / T, T>>>(ei, E, EE, out);
    k_fin2<<<(n * 16 + T - 1) / T, T>>>(out, b2, n);
}

// round 2
// speedup vs baseline: 1.1970x; 1.1970x over previous
#include <cuda_runtime.h>
#include <cstdint>

// Problem constants (fixed by the dataset)
#define NN   100000
#define EMAX 3200000

// ---------------- scratch (device globals; no allocation allowed) ----------
__device__ float g_h1  [NN * 16];   // layer1 transformed features
__device__ float g_out1[NN * 16];   // layer1 raw aggregate (unnormalized)
__device__ float g_h2  [NN * 64];   // layer2 transformed features
__device__ float g_as  [NN];        // alpha_src per node (reused across layers)
__device__ float g_ad  [NN];        // alpha_dst per node
__device__ float g_s   [NN];        // layer1 segment sum of p
__device__ float g_s2  [NN];        // layer2 segment sum of p
__device__ float g_w1a [4];         // W1 @ a_src1 (2), W1 @ a_dst1 (2)
__device__ float g_w2a [32];        // W2 @ a_src2 (16), W2 @ a_dst2 (16)

// ---------------- helpers ---------------------------------------------------
__device__ __forceinline__ float lrelu(float v) {
    return v > 0.f ? v : 0.2f * v;
}
__device__ __forceinline__ void red_add_v4(float* ptr, float4 v) {
    asm volatile("red.global.add.v4.f32 [%0], {%1,%2,%3,%4};"
                 :: "l"(ptr), "f"(v.x), "f"(v.y), "f"(v.z), "f"(v.w)
                 : "memory");
}

// ---------------- tiny precompute: project attention vectors through W -----
__global__ void k_prep(const float* __restrict__ W1, const float* __restrict__ as1,
                       const float* __restrict__ ad1,
                       const float* __restrict__ W2, const float* __restrict__ as2,
                       const float* __restrict__ ad2) {
    int t = threadIdx.x;
    if (t < 2) {
        float s = 0.f, d = 0.f;
        #pragma unroll
        for (int f = 0; f < 16; f++) {
            s += W1[t * 16 + f] * as1[f];
            d += W1[t * 16 + f] * ad1[f];
        }
        g_w1a[t] = s; g_w1a[2 + t] = d;
    }
    if (t < 16) {
        float s = 0.f, d = 0.f;
        #pragma unroll
        for (int f = 0; f < 64; f++) {
            s += W2[t * 64 + f] * as2[f];
            d += W2[t * 64 + f] * ad2[f];
        }
        g_w2a[t] = s; g_w2a[16 + t] = d;
    }
}

// ---------------- layer 1 node pass: h1 = x@W1, alpha, init, zero agg ------
__global__ void k_l1_node(const float* __restrict__ x, const float* __restrict__ W1, int n) {
    int i = blockIdx.x * blockDim.x + threadIdx.x;
    if (i >= n) return;
    float x0 = x[2 * i], x1 = x[2 * i + 1];
    float4 z = make_float4(0.f, 0.f, 0.f, 0.f);
    #pragma unroll
    for (int g = 0; g < 4; g++) {
        float4 w0 = __ldg(((const float4*)W1) + g);      // row 0
        float4 w1 = __ldg(((const float4*)W1) + 4 + g);  // row 1
        float4 h;
        h.x = x0 * w0.x + x1 * w1.x;
        h.y = x0 * w0.y + x1 * w1.y;
        h.z = x0 * w0.z + x1 * w1.z;
        h.w = x0 * w0.w + x1 * w1.w;
        ((float4*)(g_h1 + i * 16))[g]   = h;
        ((float4*)(g_out1 + i * 16))[g] = z;
    }
    g_as[i] = x0 * g_w1a[0] + x1 * g_w1a[1];
    g_ad[i] = x0 * g_w1a[2] + x1 * g_w1a[3];
    g_s[i]  = 0.f;
}

// ---------------- layer 1 edge aggregate: 4 lanes/edge (F=16) --------------
// No max-subtraction: softmax is shift-invariant and logits are small enough
// that exp() cannot overflow fp32.
__global__ void k_agg1(const int* __restrict__ ei, int E, int EE) {
    int gid  = blockIdx.x * blockDim.x + threadIdx.x;
    int e    = gid >> 2;
    int lane = gid & 3;
    if (e >= EE) return;
    int src, dst;
    if (e < E) { src = ei[e]; dst = ei[E + e]; }
    else       { src = dst = e - E; }
    float v = lrelu(g_as[src] + g_ad[dst]);
    float p = __expf(v);
    if (lane == 0) atomicAdd(&g_s[dst], p);
    float4 hv = *(const float4*)(g_h1 + src * 16 + lane * 4);
    float4 r  = make_float4(p * hv.x, p * hv.y, p * hv.z, p * hv.w);
    red_add_v4(g_out1 + dst * 16 + lane * 4, r);
}

// ---------------- layer 2 node pass (fused layer-1 epilogue) ----------------
// in_k = relu(agg_k / s + b1_k); then h2 = in @ W2, alphas, init g_s2.
__global__ void k_l2_node(const float* __restrict__ W2, const float* __restrict__ b1, int n) {
    int idx = blockIdx.x * blockDim.x + threadIdx.x;  // node*16 float4-groups
    if (idx >= n * 16) return;
    int node = idx >> 4, g = idx & 15;

    float sinv = 1.f / g_s[node];
    float in[16];
    #pragma unroll
    for (int j = 0; j < 4; j++) {
        float4 a  = ((const float4*)(g_out1 + node * 16))[j];
        float4 bb = __ldg(((const float4*)b1) + j);
        in[4 * j + 0] = fmaxf(a.x * sinv + bb.x, 0.f);
        in[4 * j + 1] = fmaxf(a.y * sinv + bb.y, 0.f);
        in[4 * j + 2] = fmaxf(a.z * sinv + bb.z, 0.f);
        in[4 * j + 3] = fmaxf(a.w * sinv + bb.w, 0.f);
    }

    float4 acc = make_float4(0.f, 0.f, 0.f, 0.f);
    #pragma unroll
    for (int k = 0; k < 16; k++) {
        float ik = in[k];
        float4 w = __ldg(((const float4*)W2) + k * 16 + g);
        acc.x += ik * w.x;
        acc.y += ik * w.y;
        acc.z += ik * w.z;
        acc.w += ik * w.w;
    }
    ((float4*)(g_h2 + node * 64))[g] = acc;

    if (g == 0) {
        float s = 0.f, d = 0.f;
        #pragma unroll
        for (int k = 0; k < 16; k++) {
            s += in[k] * g_w2a[k];
            d += in[k] * g_w2a[16 + k];
        }
        g_as[node] = s;
        g_ad[node] = d;
        g_s2[node] = 0.f;
    }
}

// ---------------- layer 2 edge aggregate: 16 lanes/edge (F=64) --------------
__global__ void k_agg2(const int* __restrict__ ei, int E, int EE, float* __restrict__ out) {
    int gid  = blockIdx.x * blockDim.x + threadIdx.x;
    int e    = gid >> 4;
    int lane = gid & 15;
    if (e >= EE) return;
    int src, dst;
    if (e < E) { src = ei[e]; dst = ei[E + e]; }
    else       { src = dst = e - E; }
    float v = lrelu(g_as[src] + g_ad[dst]);
    float p = __expf(v);
    if (lane == 0) atomicAdd(&g_s2[dst], p);
    float4 hv = *(const float4*)(g_h2 + src * 64 + lane * 4);
    float4 r  = make_float4(p * hv.x, p * hv.y, p * hv.z, p * hv.w);
    red_add_v4(out + dst * 64 + lane * 4, r);
}

// ---------------- layer 2 epilogue: out = relu(out/s2 + b2) -----------------
__global__ void k_fin2(float* __restrict__ out, const float* __restrict__ b2, int n) {
    int idx = blockIdx.x * blockDim.x + threadIdx.x;  // node*16 float4-groups
    if (idx >= n * 16) return;
    int node = idx >> 4, g = idx & 15;
    float sinv = 1.f / g_s2[node];
    float4 a  = ((float4*)out)[idx];
    float4 bb = __ldg(((const float4*)b2) + g);
    a.x = fmaxf(a.x * sinv + bb.x, 0.f);
    a.y = fmaxf(a.y * sinv + bb.y, 0.f);
    a.z = fmaxf(a.z * sinv + bb.z, 0.f);
    a.w = fmaxf(a.w * sinv + bb.w, 0.f);
    ((float4*)out)[idx] = a;
}

// ---------------- launch -----------------------------------------------------
extern "C" void kernel_launch(void* const* d_in, const int* in_sizes, int n_in,
                              void* d_out, int out_size) {
    const float* x   = (const float*)d_in[0];
    const int*   ei  = (const int*)  d_in[1];
    const float* W1  = (const float*)d_in[2];
    const float* as1 = (const float*)d_in[3];
    const float* ad1 = (const float*)d_in[4];
    const float* b1  = (const float*)d_in[5];
    const float* W2  = (const float*)d_in[6];
    const float* as2 = (const float*)d_in[7];
    const float* ad2 = (const float*)d_in[8];
    const float* b2  = (const float*)d_in[9];
    float* out = (float*)d_out;

    int n  = in_sizes[0] / 2;   // N = 100000
    int E  = in_sizes[1] / 2;   // 3.2M
    int EE = E + n;             // with self-loops

    const int T = 256;

    k_prep<<<1, 64>>>(W1, as1, ad1, W2, as2, ad2);

    // ---- layer 1 ----
    k_l1_node<<<(n + T - 1) / T, T>>>(x, W1, n);
    k_agg1<<<(EE * 4 + T - 1) / T, T>>>(ei, E, EE);

    // ---- layer 2 (fin1 fused into l2_node) ----
    k_l2_node<<<(n * 16 + T - 1) / T, T>>>(W2, b1, n);
    cudaMemsetAsync(out, 0, (size_t)out_size * sizeof(float), 0);
    k_agg2<<<(EE * 16 + T - 1) / T, T>>>(ei, E, EE, out);
    k_fin2<<<(n * 16 + T - 1) / T, T>>>(out, b2, n);
}

// round 3
// speedup vs baseline: 2.0746x; 1.7331x over previous
#include <cuda_runtime.h>
#include <cstdint>

#define NN    100000
#define EMAX  3200000
#define EEMAX (EMAX + NN)

// ---------------- scratch (device globals) ----------------------------------
__device__ float g_h1  [NN * 16];
__device__ float g_out1[NN * 16];
__device__ float g_h2  [NN * 64];
__device__ float g_as  [NN];
__device__ float g_ad  [NN];
__device__ float g_w1a [4];
__device__ float g_w2a [32];
// CSR
__device__ int   g_deg [NN];
__device__ int   g_off [NN];
__device__ int   g_cur [NN];
__device__ int   g_srcl[EEMAX];
__device__ int   g_bsum[128];
__device__ int   g_bpre[128];

__device__ __forceinline__ float lrelu(float v) { return v > 0.f ? v : 0.2f * v; }

// ---------------- prep: project attention vectors through W -----------------
__global__ void k_prep(const float* __restrict__ W1, const float* __restrict__ as1,
                       const float* __restrict__ ad1,
                       const float* __restrict__ W2, const float* __restrict__ as2,
                       const float* __restrict__ ad2) {
    int t = threadIdx.x;
    if (t < 2) {
        float s = 0.f, d = 0.f;
        #pragma unroll
        for (int f = 0; f < 16; f++) { s += W1[t*16+f]*as1[f]; d += W1[t*16+f]*ad1[f]; }
        g_w1a[t] = s; g_w1a[2+t] = d;
    }
    if (t < 16) {
        float s = 0.f, d = 0.f;
        #pragma unroll
        for (int f = 0; f < 64; f++) { s += W2[t*64+f]*as2[f]; d += W2[t*64+f]*ad2[f]; }
        g_w2a[t] = s; g_w2a[16+t] = d;
    }
}

// ---------------- layer1 node: h1 = x@W1, alphas, deg=1 (self-loop) ---------
__global__ void k_l1_node(const float* __restrict__ x, const float* __restrict__ W1, int n) {
    int i = blockIdx.x * blockDim.x + threadIdx.x;
    if (i >= n) return;
    float x0 = x[2*i], x1 = x[2*i+1];
    #pragma unroll
    for (int g = 0; g < 4; g++) {
        float4 w0 = __ldg(((const float4*)W1) + g);
        float4 w1 = __ldg(((const float4*)W1) + 4 + g);
        float4 h;
        h.x = x0*w0.x + x1*w1.x;
        h.y = x0*w0.y + x1*w1.y;
        h.z = x0*w0.z + x1*w1.z;
        h.w = x0*w0.w + x1*w1.w;
        ((float4*)(g_h1 + i*16))[g] = h;
    }
    g_as[i]  = x0*g_w1a[0] + x1*g_w1a[1];
    g_ad[i]  = x0*g_w1a[2] + x1*g_w1a[3];
    g_deg[i] = 1;   // self loop
}

// ---------------- CSR build --------------------------------------------------
__global__ void k_hist(const int* __restrict__ ei, int E) {
    int e = blockIdx.x * blockDim.x + threadIdx.x;
    if (e >= E) return;
    atomicAdd(&g_deg[ei[E + e]], 1);
}

#define SCAN_BLK 1024
__global__ void k_scan1(int n) {
    __shared__ int sh[SCAN_BLK];
    int i = blockIdx.x * SCAN_BLK + threadIdx.x;
    int v = (i < n) ? g_deg[i] : 0;
    sh[threadIdx.x] = v;
    __syncthreads();
    #pragma unroll
    for (int o = 1; o < SCAN_BLK; o <<= 1) {
        int t = (threadIdx.x >= o) ? sh[threadIdx.x - o] : 0;
        __syncthreads();
        sh[threadIdx.x] += t;
        __syncthreads();
    }
    if (i < n) g_off[i] = sh[threadIdx.x] - v;              // exclusive
    if (threadIdx.x == SCAN_BLK - 1) g_bsum[blockIdx.x] = sh[threadIdx.x];
}
__global__ void k_scan2(int nb) {
    if (threadIdx.x == 0) {
        int run = 0;
        for (int b = 0; b < nb; b++) { g_bpre[b] = run; run += g_bsum[b]; }
    }
}
__global__ void k_scan3(int n) {
    int i = blockIdx.x * blockDim.x + threadIdx.x;
    if (i >= n) return;
    int o = g_off[i] + g_bpre[i >> 10];
    g_off[i] = o;
    g_cur[i] = o;
}
__global__ void k_scatter(const int* __restrict__ ei, int E, int EE) {
    int e = blockIdx.x * blockDim.x + threadIdx.x;
    if (e >= EE) return;
    int src, dst;
    if (e < E) { src = ei[e]; dst = ei[E + e]; }
    else       { src = dst = e - E; }
    int pos = atomicAdd(&g_cur[dst], 1);
    g_srcl[pos] = src;
}

// ---------------- layer1 aggregate: warp per dst node, 4 lanes/edge ---------
// out1 = relu( (sum_e p_e * h1[src_e]) / sum_e p_e + b1 )
__global__ void k_agg1_csr(const float* __restrict__ b1, int n) {
    int warp = (blockIdx.x * blockDim.x + threadIdx.x) >> 5;
    if (warp >= n) return;
    int lane = threadIdx.x & 31;
    int sub  = lane >> 2, fl = lane & 3;
    int start = g_off[warp], deg = g_deg[warp];
    float adv = g_ad[warp];
    float4 acc = make_float4(0.f, 0.f, 0.f, 0.f);
    float psum = 0.f;
    for (int i = sub; i < deg; i += 8) {
        int src = g_srcl[start + i];
        float p = __expf(lrelu(g_as[src] + adv));
        if (fl == 0) psum += p;
        float4 hv = *(const float4*)(g_h1 + src * 16 + fl * 4);
        acc.x += p * hv.x; acc.y += p * hv.y;
        acc.z += p * hv.z; acc.w += p * hv.w;
    }
    #pragma unroll
    for (int o = 4; o < 32; o <<= 1) {
        acc.x += __shfl_xor_sync(0xffffffffu, acc.x, o);
        acc.y += __shfl_xor_sync(0xffffffffu, acc.y, o);
        acc.z += __shfl_xor_sync(0xffffffffu, acc.z, o);
        acc.w += __shfl_xor_sync(0xffffffffu, acc.w, o);
        psum  += __shfl_xor_sync(0xffffffffu, psum,  o);
    }
    float pt = __shfl_sync(0xffffffffu, psum, 0);
    if (lane < 4) {
        float sinv = 1.f / pt;
        float4 bb = __ldg(((const float4*)b1) + lane);
        float4 r;
        r.x = fmaxf(acc.x * sinv + bb.x, 0.f);
        r.y = fmaxf(acc.y * sinv + bb.y, 0.f);
        r.z = fmaxf(acc.z * sinv + bb.z, 0.f);
        r.w = fmaxf(acc.w * sinv + bb.w, 0.f);
        ((float4*)(g_out1 + warp * 16))[lane] = r;
    }
}

// ---------------- layer2 node: h2 = out1@W2 (smem-tiled), alphas -------------
__global__ void k_l2_node(const float* __restrict__ W2, int n) {
    __shared__ float4 sW4[256];           // W2: 16x64 floats = 256 float4
    __shared__ float  sin[16][16];        // 16 nodes x 16 feats
    float* sW = (float*)sW4;
    int tid = threadIdx.x;
    if (tid < 256) {
        sW[tid]       = W2[tid];
        sW[tid + 256] = W2[tid + 256];
        sW[tid + 512] = W2[tid + 512];
        sW[tid + 768] = W2[tid + 768];
    }
    int node0 = blockIdx.x * 16;
    int gidx  = node0 * 16 + tid;         // coalesced stage of out1
    if (gidx < n * 16) sin[tid >> 4][tid & 15] = g_out1[gidx];
    __syncthreads();

    int node = node0 + (tid >> 4);
    if (node >= n) return;
    int g = tid & 15;
    const float* in = sin[tid >> 4];
    float4 acc = make_float4(0.f, 0.f, 0.f, 0.f);
    #pragma unroll
    for (int k = 0; k < 16; k++) {
        float ik = in[k];
        float4 w = sW4[k * 16 + g];
        acc.x += ik * w.x; acc.y += ik * w.y;
        acc.z += ik * w.z; acc.w += ik * w.w;
    }
    ((float4*)(g_h2 + node * 64))[g] = acc;
    if (g == 0) {
        float s = 0.f, d = 0.f;
        #pragma unroll
        for (int k = 0; k < 16; k++) {
            s += in[k] * g_w2a[k];
            d += in[k] * g_w2a[16 + k];
        }
        g_as[node] = s;
        g_ad[node] = d;
    }
}

// ---------------- layer2 aggregate: warp per dst node, 16 lanes/edge --------
// out = relu( (sum_e p_e * h2[src_e]) / sum_e p_e + b2 ), written once, coalesced
__global__ void k_agg2_csr(const float* __restrict__ b2, float* __restrict__ out, int n) {
    int warp = (blockIdx.x * blockDim.x + threadIdx.x) >> 5;
    if (warp >= n) return;
    int lane = threadIdx.x & 31;
    int hl = lane >> 4, fl = lane & 15;
    int start = g_off[warp], deg = g_deg[warp];
    float adv = g_ad[warp];
    float4 acc = make_float4(0.f, 0.f, 0.f, 0.f);
    float psum = 0.f;
    for (int i = hl; i < deg; i += 2) {
        int src = g_srcl[start + i];
        float p = __expf(lrelu(g_as[src] + adv));
        if (fl == 0) psum += p;
        float4 hv = *(const float4*)(g_h2 + src * 64 + fl * 4);
        acc.x += p * hv.x; acc.y += p * hv.y;
        acc.z += p * hv.z; acc.w += p * hv.w;
    }
    acc.x += __shfl_xor_sync(0xffffffffu, acc.x, 16);
    acc.y += __shfl_xor_sync(0xffffffffu, acc.y, 16);
    acc.z += __shfl_xor_sync(0xffffffffu, acc.z, 16);
    acc.w += __shfl_xor_sync(0xffffffffu, acc.w, 16);
    psum  += __shfl_xor_sync(0xffffffffu, psum,  16);
    float pt = __shfl_sync(0xffffffffu, psum, 0);
    if (lane < 16) {
        float sinv = 1.f / pt;
        float4 bb = __ldg(((const float4*)b2) + lane);
        float4 r;
        r.x = fmaxf(acc.x * sinv + bb.x, 0.f);
        r.y = fmaxf(acc.y * sinv + bb.y, 0.f);
        r.z = fmaxf(acc.z * sinv + bb.z, 0.f);
        r.w = fmaxf(acc.w * sinv + bb.w, 0.f);
        ((float4*)(out + warp * 64))[lane] = r;
    }
}

// ---------------- launch -----------------------------------------------------
extern "C" void kernel_launch(void* const* d_in, const int* in_sizes, int n_in,
                              void* d_out, int out_size) {
    const float* x   = (const float*)d_in[0];
    const int*   ei  = (const int*)  d_in[1];
    const float* W1  = (const float*)d_in[2];
    const float* as1 = (const float*)d_in[3];
    const float* ad1 = (const float*)d_in[4];
    const float* b1  = (const float*)d_in[5];
    const float* W2  = (const float*)d_in[6];
    const float* as2 = (const float*)d_in[7];
    const float* ad2 = (const float*)d_in[8];
    const float* b2  = (const float*)d_in[9];
    float* out = (float*)d_out;

    int n  = in_sizes[0] / 2;   // 100000
    int E  = in_sizes[1] / 2;   // 3.2M
    int EE = E + n;

    const int T = 256;
    int nb = (n + SCAN_BLK - 1) / SCAN_BLK;

    k_prep<<<1, 64>>>(W1, as1, ad1, W2, as2, ad2);
    k_l1_node<<<(n + T - 1) / T, T>>>(x, W1, n);

    // CSR build
    k_hist<<<(E + T - 1) / T, T>>>(ei, E);
    k_scan1<<<nb, SCAN_BLK>>>(n);
    k_scan2<<<1, 32>>>(nb);
    k_scan3<<<(n + T - 1) / T, T>>>(n);
    k_scatter<<<(EE + T - 1) / T, T>>>(ei, E, EE);

    // layer 1 aggregate (normalize+bias+relu fused)
    k_agg1_csr<<<(n * 32 + T - 1) / T, T>>>(b1, n);

    // layer 2
    k_l2_node<<<(n + 15) / 16, T>>>(W2, n);
    k_agg2_csr<<<(n * 32 + T - 1) / T, T>>>(b2, out, n);
}

// round 5
// speedup vs baseline: 2.6666x; 1.2854x over previous
#include <cuda_runtime.h>
#include <cstdint>

#define NN    100000
#define EMAX  3200000
#define EEMAX (EMAX + NN)
#define FULL  0xffffffffu

// ---------------- scratch (device globals) ----------------------------------
__device__ float g_out1[NN * 16];   // layer1 output (post relu)
__device__ float g_ad  [NN];        // alpha_dst (layer1 then layer2, per node)
__device__ float g_w1a [4];         // W1@a_src1 (2), W1@a_dst1 (2)
__device__ float g_w2a [32];        // W2@a_src2 (16), W2@a_dst2 (16)
// CSR
__device__ int   g_deg [NN];
__device__ int   g_off [NN];
__device__ int   g_cur [NN];
__device__ int   g_srcl[EEMAX];
__device__ int   g_bsum[128];
__device__ int   g_bpre[128];

__device__ __forceinline__ float lrelu(float v) { return v > 0.f ? v : 0.2f * v; }

// ---------------- prep: project attention vectors through W -----------------
__global__ void k_prep(const float* __restrict__ W1, const float* __restrict__ as1,
                       const float* __restrict__ ad1,
                       const float* __restrict__ W2, const float* __restrict__ as2,
                       const float* __restrict__ ad2) {
    int t = threadIdx.x;
    if (t < 2) {
        float s = 0.f, d = 0.f;
        #pragma unroll
        for (int f = 0; f < 16; f++) { s += W1[t*16+f]*as1[f]; d += W1[t*16+f]*ad1[f]; }
        g_w1a[t] = s; g_w1a[2+t] = d;
    }
    if (t < 16) {
        float s = 0.f, d = 0.f;
        #pragma unroll
        for (int f = 0; f < 64; f++) { s += W2[t*64+f]*as2[f]; d += W2[t*64+f]*ad2[f]; }
        g_w2a[t] = s; g_w2a[16+t] = d;
    }
}

// ---------------- node init: alpha_dst1, deg=1 (self loop) -------------------
__global__ void k_l1_node(const float* __restrict__ x, int n) {
    int i = blockIdx.x * blockDim.x + threadIdx.x;
    if (i >= n) return;
    float2 xv = ((const float2*)x)[i];
    g_ad[i]  = xv.x * g_w1a[2] + xv.y * g_w1a[3];
    g_deg[i] = 1;
}

// ---------------- CSR build --------------------------------------------------
__global__ void k_hist(const int* __restrict__ ei, int E) {
    int e = blockIdx.x * blockDim.x + threadIdx.x;
    if (e >= E) return;
    atomicAdd(&g_deg[ei[E + e]], 1);
}

#define SCAN_BLK 1024
__global__ void k_scan1(int n) {   // warp-shuffle block scan (exclusive in g_off)
    __shared__ int wsum[32];
    int i = blockIdx.x * SCAN_BLK + threadIdx.x;
    int lane = threadIdx.x & 31, w = threadIdx.x >> 5;
    int v = (i < n) ? g_deg[i] : 0;
    int s = v;
    #pragma unroll
    for (int o = 1; o < 32; o <<= 1) {
        int t = __shfl_up_sync(FULL, s, o);
        if (lane >= o) s += t;
    }
    if (lane == 31) wsum[w] = s;
    __syncthreads();
    if (w == 0) {
        int ws = wsum[lane];
        #pragma unroll
        for (int o = 1; o < 32; o <<= 1) {
            int t = __shfl_up_sync(FULL, ws, o);
            if (lane >= o) ws += t;
        }
        wsum[lane] = ws;
    }
    __syncthreads();
    int base = (w > 0) ? wsum[w - 1] : 0;
    if (i < n) g_off[i] = base + s - v;                     // exclusive
    if (threadIdx.x == SCAN_BLK - 1) g_bsum[blockIdx.x] = base + s;
}
__global__ void k_scan2(int nb) {   // scan <=128 block sums, one block
    __shared__ int sh[128];
    int t = threadIdx.x;
    sh[t] = (t < nb) ? g_bsum[t] : 0;
    __syncthreads();
    #pragma unroll
    for (int o = 1; o < 128; o <<= 1) {
        int v = (t >= o) ? sh[t - o] : 0;
        __syncthreads();
        sh[t] += v;
        __syncthreads();
    }
    if (t < nb) g_bpre[t] = sh[t] - g_bsum[t];              // exclusive
}
__global__ void k_scan3(int n) {
    int i = blockIdx.x * blockDim.x + threadIdx.x;
    if (i >= n) return;
    int o = g_off[i] + g_bpre[i >> 10];
    g_off[i] = o;
    g_cur[i] = o;
}
__global__ void k_scatter(const int* __restrict__ ei, int E, int EE) {
    int e = blockIdx.x * blockDim.x + threadIdx.x;
    if (e >= EE) return;
    int src, dst;
    if (e < E) { src = ei[e]; dst = ei[E + e]; }
    else       { src = dst = e - E; }
    int pos = atomicAdd(&g_cur[dst], 1);
    g_srcl[pos] = src;
}

// ---------------- layer1 aggregate: warp/dst, 1 lane/edge, linearity trick --
// acc = (sum_e p_e * x[src_e]); out1 = relu(acc@W1 / sum_e p_e + b1)
// Also computes alpha_dst for layer 2 and stores into g_ad.
__global__ void k_agg1_csr(const float* __restrict__ x, const float* __restrict__ W1,
                           const float* __restrict__ b1, int n) {
    int warp = (blockIdx.x * blockDim.x + threadIdx.x) >> 5;
    if (warp >= n) return;
    int lane  = threadIdx.x & 31;
    int start = g_off[warp], deg = g_deg[warp];
    float adv = g_ad[warp];
    float wa0 = g_w1a[0], wa1 = g_w1a[1];
    float psum = 0.f, px0 = 0.f, px1 = 0.f;
    for (int i = lane; i < deg; i += 32) {
        int src = g_srcl[start + i];
        float2 xv = ((const float2*)x)[src];
        float p = __expf(lrelu(xv.x * wa0 + xv.y * wa1 + adv));
        psum += p; px0 += p * xv.x; px1 += p * xv.y;
    }
    #pragma unroll
    for (int o = 16; o >= 1; o >>= 1) {       // post-loop: warp fully convergent
        psum += __shfl_xor_sync(FULL, psum, o);
        px0  += __shfl_xor_sync(FULL, px0,  o);
        px1  += __shfl_xor_sync(FULL, px1,  o);
    }
    if (lane < 16) {
        float sinv = 1.f / psum;
        float v = fmaxf((px0 * __ldg(W1 + lane) + px1 * __ldg(W1 + 16 + lane)) * sinv
                        + __ldg(b1 + lane), 0.f);
        g_out1[warp * 16 + lane] = v;
        // alpha_dst for layer 2 = out1_row . w2a_d
        float pd = v * g_w2a[16 + lane];
        #pragma unroll
        for (int o = 8; o >= 1; o >>= 1)
            pd += __shfl_xor_sync(0xffffu, pd, o);
        if (lane == 0) g_ad[warp] = pd;
    }
}

// ---------------- layer2 aggregate: warp/dst, 4 lanes/edge, linearity trick -
// t = (sum_e p_e * out1[src_e]) / sum_e p_e ; out = relu(t@W2 + b2)
// NOTE: trip count is warp-uniform; tail is predicated so the intra-subgroup
// shuffles are always executed by all 32 lanes (validity uniform per subgroup).
__global__ void k_agg2_csr(const float* __restrict__ W2, const float* __restrict__ b2,
                           float* __restrict__ out, int n) {
    __shared__ float sW[1024];   // W2 16x64
    for (int i = threadIdx.x; i < 1024; i += blockDim.x) sW[i] = W2[i];
    __syncthreads();

    int warp = (blockIdx.x * blockDim.x + threadIdx.x) >> 5;
    if (warp >= n) return;
    int lane = threadIdx.x & 31;
    int fl   = lane & 3;             // feature slice (4 floats)
    int sub  = lane >> 2;            // 8 edges in parallel
    int start = g_off[warp], deg = g_deg[warp];
    float adv = g_ad[warp];
    float wsa = g_w2a[fl * 4 + 0], wsb = g_w2a[fl * 4 + 1];
    float wsc = g_w2a[fl * 4 + 2], wsd = g_w2a[fl * 4 + 3];

    float4 acc = make_float4(0.f, 0.f, 0.f, 0.f);
    float psum = 0.f;
    int iters = (deg + 7) >> 3;                // warp-uniform trip count
    for (int it = 0; it < iters; it++) {
        int i = it * 8 + sub;
        bool valid = (i < deg);
        int src = valid ? g_srcl[start + i] : 0;
        float4 hv = valid ? *(const float4*)(g_out1 + src * 16 + fl * 4)
                          : make_float4(0.f, 0.f, 0.f, 0.f);
        float pa = hv.x * wsa + hv.y * wsb + hv.z * wsc + hv.w * wsd;
        pa += __shfl_xor_sync(FULL, pa, 1);
        pa += __shfl_xor_sync(FULL, pa, 2);    // alpha_src, same in all 4 lanes
        float p = valid ? __expf(lrelu(pa + adv)) : 0.f;
        psum += p;
        acc.x += p * hv.x; acc.y += p * hv.y;
        acc.z += p * hv.z; acc.w += p * hv.w;
    }
    #pragma unroll
    for (int o = 4; o <= 16; o <<= 1) {        // reduce across the 8 subgroups
        acc.x += __shfl_xor_sync(FULL, acc.x, o);
        acc.y += __shfl_xor_sync(FULL, acc.y, o);
        acc.z += __shfl_xor_sync(FULL, acc.z, o);
        acc.w += __shfl_xor_sync(FULL, acc.w, o);
        psum  += __shfl_xor_sync(FULL, psum,  o);
    }
    // every lane now holds total psum and total acc for its fl slice
    float sinv = 1.f / psum;
    float t[16];
    #pragma unroll
    for (int k = 0; k < 16; k++) {
        float c = ((k & 3) == 0) ? acc.x : ((k & 3) == 1) ? acc.y
                 : ((k & 3) == 2) ? acc.z : acc.w;
        t[k] = __shfl_sync(FULL, c, k >> 2) * sinv;   // lane (k>>2) has fl==k>>2
    }
    // each lane produces 2 of the 64 output features
    float2 r = make_float2(0.f, 0.f);
    #pragma unroll
    for (int k = 0; k < 16; k++) {
        float2 w = *(const float2*)&sW[k * 64 + 2 * lane];
        r.x += t[k] * w.x;
        r.y += t[k] * w.y;
    }
    float2 bb = __ldg((const float2*)b2 + lane);
    r.x = fmaxf(r.x + bb.x, 0.f);
    r.y = fmaxf(r.y + bb.y, 0.f);
    ((float2*)(out + warp * 64))[lane] = r;
}

// ---------------- launch -----------------------------------------------------
extern "C" void kernel_launch(void* const* d_in, const int* in_sizes, int n_in,
                              void* d_out, int out_size) {
    const float* x   = (const float*)d_in[0];
    const int*   ei  = (const int*)  d_in[1];
    const float* W1  = (const float*)d_in[2];
    const float* as1 = (const float*)d_in[3];
    const float* ad1 = (const float*)d_in[4];
    const float* b1  = (const float*)d_in[5];
    const float* W2  = (const float*)d_in[6];
    const float* as2 = (const float*)d_in[7];
    const float* ad2 = (const float*)d_in[8];
    const float* b2  = (const float*)d_in[9];
    float* out = (float*)d_out;

    int n  = in_sizes[0] / 2;   // 100000
    int E  = in_sizes[1] / 2;   // 3.2M
    int EE = E + n;

    const int T = 256;
    int nb = (n + SCAN_BLK - 1) / SCAN_BLK;

    k_prep<<<1, 64>>>(W1, as1, ad1, W2, as2, ad2);
    k_l1_node<<<(n + T - 1) / T, T>>>(x, n);

    // CSR build (once; shared by both layers)
    k_hist<<<(E + T - 1) / T, T>>>(ei, E);
    k_scan1<<<nb, SCAN_BLK>>>(n);
    k_scan2<<<1, 128>>>(nb);
    k_scan3<<<(n + T - 1) / T, T>>>(n);
    k_scatter<<<(EE + T - 1) / T, T>>>(ei, E, EE);

    // layer 1: aggregate + transform + epilogue fused
    k_agg1_csr<<<(n * 32 + T - 1) / T, T>>>(x, W1, b1, n);
    // layer 2: aggregate + transform + epilogue fused
    k_agg2_csr<<<(n * 32 + T - 1) / T, T>>>(W2, b2, out, n);
}

// round 6
// speedup vs baseline: 2.8297x; 1.0612x over previous
#include <cuda_runtime.h>
#include <cstdint>

#define NN    100000
#define EMAX  3200000
#define EEMAX (EMAX + NN)
#define FULL  0xffffffffu

// ---------------- scratch (device globals) ----------------------------------
__device__ float g_out1[NN * 16];   // layer1 output (post relu)
__device__ float g_ad  [NN];        // alpha_dst (layer1 then layer2, per node)
__device__ float g_w1a [4];         // W1@a_src1 (2), W1@a_dst1 (2)
__device__ float g_w2a [32];        // W2@a_src2 (16), W2@a_dst2 (16)
// CSR
__device__ int   g_deg [NN];        // transient edge counts (self-cleaned by scan1)
__device__ int   g_off [NN];        // segment start
__device__ int   g_cur [NN];        // scatter cursor -> segment end after scatter
__device__ int   g_srcl[EEMAX];
__device__ int   g_bsum[128];

__device__ __forceinline__ float lrelu(float v) { return v > 0.f ? v : 0.2f * v; }

// ---------------- fused: hist (4 edges/thread) + node init + w1a/w2a --------
// g_deg must be zero on entry: zeroed at module load, then re-zeroed by k_scan1
// every call, so graph replays stay deterministic.
__global__ void k_hist_init(const int* __restrict__ ei, const float* __restrict__ x,
                            const float* __restrict__ W1, const float* __restrict__ as1,
                            const float* __restrict__ ad1,
                            const float* __restrict__ W2, const float* __restrict__ as2,
                            const float* __restrict__ ad2,
                            int E, int n) {
    int t  = blockIdx.x * blockDim.x + threadIdx.x;
    int E4 = E >> 2;
    const int* dsts = ei + E;
    if (t < E4) {
        int4 d = ((const int4*)dsts)[t];
        atomicAdd(&g_deg[d.x], 1);
        atomicAdd(&g_deg[d.y], 1);
        atomicAdd(&g_deg[d.z], 1);
        atomicAdd(&g_deg[d.w], 1);
    } else if (t == E4) {
        for (int e = E4 * 4; e < E; e++) atomicAdd(&g_deg[dsts[e]], 1);
    }
    if (t < n) {
        // local projection of a_dst1 through W1 (rows of W1 are [2][16])
        float d0 = 0.f, d1 = 0.f;
        #pragma unroll
        for (int f = 0; f < 16; f++) {
            float a = __ldg(ad1 + f);
            d0 += __ldg(W1 + f) * a;
            d1 += __ldg(W1 + 16 + f) * a;
        }
        float2 xv = ((const float2*)x)[t];
        g_ad[t] = xv.x * d0 + xv.y * d1;
    }
    if (t < 2) {   // g_w1a (needed by agg1)
        float s = 0.f, d = 0.f;
        #pragma unroll
        for (int f = 0; f < 16; f++) {
            s += __ldg(W1 + t * 16 + f) * __ldg(as1 + f);
            d += __ldg(W1 + t * 16 + f) * __ldg(ad1 + f);
        }
        g_w1a[t] = s; g_w1a[2 + t] = d;
    }
    if (t < 16) {  // g_w2a (needed by agg1 epilogue / agg2)
        float s = 0.f, d = 0.f;
        #pragma unroll
        for (int f = 0; f < 64; f++) {
            s += __ldg(W2 + t * 64 + f) * __ldg(as2 + f);
            d += __ldg(W2 + t * 64 + f) * __ldg(ad2 + f);
        }
        g_w2a[t] = s; g_w2a[16 + t] = d;
    }
}

// ---------------- scan phase 1: per-1024 block scan of (deg+1) --------------
#define SCAN_BLK 1024
__global__ void k_scan1(int n) {
    __shared__ int wsum[32];
    int i = blockIdx.x * SCAN_BLK + threadIdx.x;
    int lane = threadIdx.x & 31, w = threadIdx.x >> 5;
    int v = 0;
    if (i < n) {
        v = g_deg[i] + 1;      // +1 = self loop
        g_deg[i] = 0;          // self-clean for next replay
    }
    int s = v;
    #pragma unroll
    for (int o = 1; o < 32; o <<= 1) {
        int t = __shfl_up_sync(FULL, s, o);
        if (lane >= o) s += t;
    }
    if (lane == 31) wsum[w] = s;
    __syncthreads();
    if (w == 0) {
        int ws = wsum[lane];
        #pragma unroll
        for (int o = 1; o < 32; o <<= 1) {
            int t = __shfl_up_sync(FULL, ws, o);
            if (lane >= o) ws += t;
        }
        wsum[lane] = ws;
    }
    __syncthreads();
    int base = (w > 0) ? wsum[w - 1] : 0;
    if (i < n) g_off[i] = base + s - v;                     // exclusive
    if (threadIdx.x == SCAN_BLK - 1) g_bsum[blockIdx.x] = base + s;
}

// ---------------- scan phase 2+3 fused: add block prefix, init cursors ------
// Each 256-thread block covers indices within ONE 1024-wide scan1 block, so a
// single block-prefix value (sum of g_bsum[j], j < blockIdx>>2) serves all.
__global__ void k_scan23(int n) {
    __shared__ int sbase;
    if (threadIdx.x < 32) {
        int q = blockIdx.x >> 2;        // scan1 block index
        int val = 0;
        for (int j = (int)threadIdx.x; j < q; j += 32) val += g_bsum[j];
        #pragma unroll
        for (int o = 16; o >= 1; o >>= 1) val += __shfl_xor_sync(FULL, val, o);
        if (threadIdx.x == 0) sbase = val;
    }
    __syncthreads();
    int i = blockIdx.x * 256 + threadIdx.x;
    if (i >= n) return;
    int o = g_off[i] + sbase;
    g_off[i] = o;
    g_cur[i] = o;
}

// ---------------- scatter: 4 edges/thread + self loops ----------------------
__global__ void k_scatter(const int* __restrict__ ei, int E, int n) {
    int t  = blockIdx.x * blockDim.x + threadIdx.x;
    int E4 = E >> 2;
    int base = (E + 3) >> 2;
    if (t < E4) {
        int4 s = ((const int4*)ei)[t];
        int4 d = ((const int4*)(ei + E))[t];
        g_srcl[atomicAdd(&g_cur[d.x], 1)] = s.x;
        g_srcl[atomicAdd(&g_cur[d.y], 1)] = s.y;
        g_srcl[atomicAdd(&g_cur[d.z], 1)] = s.z;
        g_srcl[atomicAdd(&g_cur[d.w], 1)] = s.w;
    } else if (t < base) {
        for (int e = E4 * 4; e < E; e++)
            g_srcl[atomicAdd(&g_cur[ei[E + e]], 1)] = ei[e];
    } else if (t - base < n) {
        int i = t - base;                 // self loop
        g_srcl[atomicAdd(&g_cur[i], 1)] = i;
    }
}

// ---------------- layer1 aggregate: warp/dst, 1 lane/edge, linearity trick --
__global__ void k_agg1_csr(const float* __restrict__ x, const float* __restrict__ W1,
                           const float* __restrict__ b1, int n) {
    int warp = (blockIdx.x * blockDim.x + threadIdx.x) >> 5;
    if (warp >= n) return;
    int lane  = threadIdx.x & 31;
    int start = g_off[warp];
    int deg   = g_cur[warp] - start;
    float adv = g_ad[warp];
    float wa0 = g_w1a[0], wa1 = g_w1a[1];
    float psum = 0.f, px0 = 0.f, px1 = 0.f;
    for (int i = lane; i < deg; i += 32) {
        int src = g_srcl[start + i];
        float2 xv = ((const float2*)x)[src];
        float p = __expf(lrelu(xv.x * wa0 + xv.y * wa1 + adv));
        psum += p; px0 += p * xv.x; px1 += p * xv.y;
    }
    #pragma unroll
    for (int o = 16; o >= 1; o >>= 1) {       // post-loop: warp fully convergent
        psum += __shfl_xor_sync(FULL, psum, o);
        px0  += __shfl_xor_sync(FULL, px0,  o);
        px1  += __shfl_xor_sync(FULL, px1,  o);
    }
    if (lane < 16) {
        float sinv = 1.f / psum;
        float v = fmaxf((px0 * __ldg(W1 + lane) + px1 * __ldg(W1 + 16 + lane)) * sinv
                        + __ldg(b1 + lane), 0.f);
        g_out1[warp * 16 + lane] = v;
        float pd = v * g_w2a[16 + lane];      // alpha_dst for layer 2
        #pragma unroll
        for (int o = 8; o >= 1; o >>= 1)
            pd += __shfl_xor_sync(0xffffu, pd, o);
        if (lane == 0) g_ad[warp] = pd;
    }
}

// ---------------- layer2 aggregate: warp/dst, 4 lanes/edge, pipelined -------
__global__ void k_agg2_csr(const float* __restrict__ W2, const float* __restrict__ b2,
                           float* __restrict__ out, int n) {
    __shared__ float sW[1024];   // W2 16x64
    for (int i = threadIdx.x; i < 1024; i += blockDim.x) sW[i] = W2[i];
    __syncthreads();

    int warp = (blockIdx.x * blockDim.x + threadIdx.x) >> 5;
    if (warp >= n) return;
    int lane = threadIdx.x & 31;
    int fl   = lane & 3;             // feature slice (4 floats)
    int sub  = lane >> 2;            // 8 edges in parallel
    int start = g_off[warp];
    int deg   = g_cur[warp] - start;
    float adv = g_ad[warp];
    float wsa = g_w2a[fl * 4 + 0], wsb = g_w2a[fl * 4 + 1];
    float wsc = g_w2a[fl * 4 + 2], wsd = g_w2a[fl * 4 + 3];

    float4 acc = make_float4(0.f, 0.f, 0.f, 0.f);
    float psum = 0.f;
    int iters = (deg + 7) >> 3;                // warp-uniform trip count

    // prologue: issue first gather
    bool  v0 = (sub < deg);
    int   s0 = v0 ? g_srcl[start + sub] : 0;
    float4 hv0 = v0 ? *(const float4*)(g_out1 + s0 * 16 + fl * 4)
                    : make_float4(0.f, 0.f, 0.f, 0.f);

    for (int it = 0; it < iters; it++) {
        // issue next gather before this iteration's dependent chain
        int i1 = (it + 1) * 8 + sub;
        bool v1 = (i1 < deg);
        int  s1 = v1 ? g_srcl[start + i1] : 0;
        float4 hv1 = v1 ? *(const float4*)(g_out1 + s1 * 16 + fl * 4)
                        : make_float4(0.f, 0.f, 0.f, 0.f);

        float pa = hv0.x * wsa + hv0.y * wsb + hv0.z * wsc + hv0.w * wsd;
        pa += __shfl_xor_sync(FULL, pa, 1);
        pa += __shfl_xor_sync(FULL, pa, 2);    // alpha_src, same in all 4 lanes
        float p = v0 ? __expf(lrelu(pa + adv)) : 0.f;
        psum += p;
        acc.x += p * hv0.x; acc.y += p * hv0.y;
        acc.z += p * hv0.z; acc.w += p * hv0.w;

        hv0 = hv1; v0 = v1;
    }
    #pragma unroll
    for (int o = 4; o <= 16; o <<= 1) {        // reduce across the 8 subgroups
        acc.x += __shfl_xor_sync(FULL, acc.x, o);
        acc.y += __shfl_xor_sync(FULL, acc.y, o);
        acc.z += __shfl_xor_sync(FULL, acc.z, o);
        acc.w += __shfl_xor_sync(FULL, acc.w, o);
        psum  += __shfl_xor_sync(FULL, psum,  o);
    }
    float sinv = 1.f / psum;
    float t[16];
    #pragma unroll
    for (int k = 0; k < 16; k++) {
        float c = ((k & 3) == 0) ? acc.x : ((k & 3) == 1) ? acc.y
                 : ((k & 3) == 2) ? acc.z : acc.w;
        t[k] = __shfl_sync(FULL, c, k >> 2) * sinv;   // lane (k>>2) has fl==k>>2
    }
    float2 r = make_float2(0.f, 0.f);
    #pragma unroll
    for (int k = 0; k < 16; k++) {
        float2 w = *(const float2*)&sW[k * 64 + 2 * lane];
        r.x += t[k] * w.x;
        r.y += t[k] * w.y;
    }
    float2 bb = __ldg((const float2*)b2 + lane);
    r.x = fmaxf(r.x + bb.x, 0.f);
    r.y = fmaxf(r.y + bb.y, 0.f);
    ((float2*)(out + warp * 64))[lane] = r;
}

// ---------------- launch -----------------------------------------------------
extern "C" void kernel_launch(void* const* d_in, const int* in_sizes, int n_in,
                              void* d_out, int out_size) {
    const float* x   = (const float*)d_in[0];
    const int*   ei  = (const int*)  d_in[1];
    const float* W1  = (const float*)d_in[2];
    const float* as1 = (const float*)d_in[3];
    const float* ad1 = (const float*)d_in[4];
    const float* b1  = (const float*)d_in[5];
    const float* W2  = (const float*)d_in[6];
    const float* as2 = (const float*)d_in[7];
    const float* ad2 = (const float*)d_in[8];
    const float* b2  = (const float*)d_in[9];
    float* out = (float*)d_out;

    int n  = in_sizes[0] / 2;   // 100000
    int E  = in_sizes[1] / 2;   // 3.2M

    const int T = 256;
    int nb   = (n + SCAN_BLK - 1) / SCAN_BLK;    (void)nb;
    int E4c  = (E + 3) >> 2;
    int hthr = (E4c + 1) > n ? (E4c + 1) : n;    // hist + node-init threads
    int sthr = E4c + n;                          // scatter threads

    k_hist_init<<<(hthr + T - 1) / T, T>>>(ei, x, W1, as1, ad1, W2, as2, ad2, E, n);
    k_scan1<<<(n + SCAN_BLK - 1) / SCAN_BLK, SCAN_BLK>>>(n);
    k_scan23<<<(n + 255) / 256, 256>>>(n);
    k_scatter<<<(sthr + T - 1) / T, T>>>(ei, E, n);
    k_agg1_csr<<<(n * 32 + T - 1) / T, T>>>(x, W1, b1, n);
    k_agg2_csr<<<(n * 32 + T - 1) / T, T>>>(W2, b2, out, n);
}

// round 7
// speedup vs baseline: 2.8823x; 1.0186x over previous
#include <cuda_runtime.h>
#include <cstdint>

#define NN    100000
#define EMAX  3200000
#define EEMAX (EMAX + NN)
#define FULL  0xffffffffu

// ---------------- scratch (device globals) ----------------------------------
__device__ float g_out1[NN * 16];   // layer1 output (post relu)
__device__ float g_ad  [NN];        // alpha_dst (layer1 then layer2, per node)
__device__ float g_w1a [4];         // W1@a_src1 (2), W1@a_dst1 (2)
__device__ float g_w2a [32];        // W2@a_src2 (16), W2@a_dst2 (16)
// CSR
__device__ int   g_deg [NN];        // transient counts (self-cleaned by scan1)
__device__ int   g_off [NN + 1];    // segment starts; g_off[n] = E+n
__device__ int   g_rank[EMAX];      // per-edge rank within dst segment
__device__ int   g_srcl[EEMAX];     // CSR adjacency (slot0 of each seg = self loop)
__device__ int   g_bsum[128];

__device__ __forceinline__ float lrelu(float v) { return v > 0.f ? v : 0.2f * v; }

// ---------------- fused: hist+rank (8 edges/thread) + node init + w1a/w2a ---
// g_deg must be zero on entry (zeroed at load; re-zeroed by k_scan1 each call).
__global__ void k_hist_init(const int* __restrict__ ei, const float* __restrict__ x,
                            const float* __restrict__ W1, const float* __restrict__ as1,
                            const float* __restrict__ ad1,
                            const float* __restrict__ W2, const float* __restrict__ as2,
                            const float* __restrict__ ad2,
                            int E, int n) {
    int t  = blockIdx.x * blockDim.x + threadIdx.x;
    int E8 = E >> 3;
    const int* dsts = ei + E;
    if (t < E8) {
        int4 d0 = ((const int4*)dsts)[2 * t];
        int4 d1 = ((const int4*)dsts)[2 * t + 1];
        int4 r0, r1;
        r0.x = atomicAdd(&g_deg[d0.x], 1);
        r0.y = atomicAdd(&g_deg[d0.y], 1);
        r0.z = atomicAdd(&g_deg[d0.z], 1);
        r0.w = atomicAdd(&g_deg[d0.w], 1);
        r1.x = atomicAdd(&g_deg[d1.x], 1);
        r1.y = atomicAdd(&g_deg[d1.y], 1);
        r1.z = atomicAdd(&g_deg[d1.z], 1);
        r1.w = atomicAdd(&g_deg[d1.w], 1);
        ((int4*)g_rank)[2 * t]     = r0;
        ((int4*)g_rank)[2 * t + 1] = r1;
    } else if (t == E8) {
        for (int e = E8 * 8; e < E; e++)
            g_rank[e] = atomicAdd(&g_deg[dsts[e]], 1);
    }
    if (t < n) {
        // local projection of a_dst1 through W1 (W1 is [2][16])
        float d0 = 0.f, d1 = 0.f;
        #pragma unroll
        for (int f = 0; f < 16; f++) {
            float a = __ldg(ad1 + f);
            d0 += __ldg(W1 + f) * a;
            d1 += __ldg(W1 + 16 + f) * a;
        }
        float2 xv = ((const float2*)x)[t];
        g_ad[t] = xv.x * d0 + xv.y * d1;
    }
    if (t < 2) {   // g_w1a
        float s = 0.f, d = 0.f;
        #pragma unroll
        for (int f = 0; f < 16; f++) {
            s += __ldg(W1 + t * 16 + f) * __ldg(as1 + f);
            d += __ldg(W1 + t * 16 + f) * __ldg(ad1 + f);
        }
        g_w1a[t] = s; g_w1a[2 + t] = d;
    }
    if (t < 16) {  // g_w2a
        float s = 0.f, d = 0.f;
        #pragma unroll
        for (int f = 0; f < 64; f++) {
            s += __ldg(W2 + t * 64 + f) * __ldg(as2 + f);
            d += __ldg(W2 + t * 64 + f) * __ldg(ad2 + f);
        }
        g_w2a[t] = s; g_w2a[16 + t] = d;
    }
}

// ---------------- scan phase 1: per-1024 block scan of (deg+1) --------------
#define SCAN_BLK 1024
__global__ void k_scan1(int n) {
    __shared__ int wsum[32];
    int i = blockIdx.x * SCAN_BLK + threadIdx.x;
    int lane = threadIdx.x & 31, w = threadIdx.x >> 5;
    int v = 0;
    if (i < n) {
        v = g_deg[i] + 1;      // +1 = self loop slot
        g_deg[i] = 0;          // self-clean for next graph replay
    }
    int s = v;
    #pragma unroll
    for (int o = 1; o < 32; o <<= 1) {
        int t = __shfl_up_sync(FULL, s, o);
        if (lane >= o) s += t;
    }
    if (lane == 31) wsum[w] = s;
    __syncthreads();
    if (w == 0) {
        int ws = wsum[lane];
        #pragma unroll
        for (int o = 1; o < 32; o <<= 1) {
            int t = __shfl_up_sync(FULL, ws, o);
            if (lane >= o) ws += t;
        }
        wsum[lane] = ws;
    }
    __syncthreads();
    int base = (w > 0) ? wsum[w - 1] : 0;
    if (i < n) g_off[i] = base + s - v;                     // exclusive
    if (threadIdx.x == SCAN_BLK - 1) g_bsum[blockIdx.x] = base + s;
}

// ---------------- scan 2+3 fused: add block prefix, place self-loops --------
__global__ void k_scan23(int n, int EE) {
    __shared__ int sbase;
    if (threadIdx.x < 32) {
        int q = blockIdx.x >> 2;        // owning scan1 block
        int val = 0;
        for (int j = (int)threadIdx.x; j < q; j += 32) val += g_bsum[j];
        #pragma unroll
        for (int o = 16; o >= 1; o >>= 1) val += __shfl_xor_sync(FULL, val, o);
        if (threadIdx.x == 0) sbase = val;
    }
    __syncthreads();
    if (blockIdx.x == 0 && threadIdx.x == 0) g_off[n] = EE;
    int i = blockIdx.x * 256 + threadIdx.x;
    if (i >= n) return;
    int o = g_off[i] + sbase;
    g_off[i]  = o;
    g_srcl[o] = i;                      // self loop at slot 0 of segment
}

// ---------------- scatter: atomic-free, 8 edges/thread ----------------------
__global__ void k_scatter(const int* __restrict__ ei, int E) {
    int t  = blockIdx.x * blockDim.x + threadIdx.x;
    int E8 = E >> 3;
    if (t < E8) {
        int4 s0 = ((const int4*)ei)[2 * t];
        int4 s1 = ((const int4*)ei)[2 * t + 1];
        int4 d0 = ((const int4*)(ei + E))[2 * t];
        int4 d1 = ((const int4*)(ei + E))[2 * t + 1];
        int4 r0 = ((const int4*)g_rank)[2 * t];
        int4 r1 = ((const int4*)g_rank)[2 * t + 1];
        g_srcl[g_off[d0.x] + 1 + r0.x] = s0.x;
        g_srcl[g_off[d0.y] + 1 + r0.y] = s0.y;
        g_srcl[g_off[d0.z] + 1 + r0.z] = s0.z;
        g_srcl[g_off[d0.w] + 1 + r0.w] = s0.w;
        g_srcl[g_off[d1.x] + 1 + r1.x] = s1.x;
        g_srcl[g_off[d1.y] + 1 + r1.y] = s1.y;
        g_srcl[g_off[d1.z] + 1 + r1.z] = s1.z;
        g_srcl[g_off[d1.w] + 1 + r1.w] = s1.w;
    } else if (t == E8) {
        for (int e = E8 * 8; e < E; e++)
            g_srcl[g_off[ei[E + e]] + 1 + g_rank[e]] = ei[e];
    }
}

// ---------------- layer1 aggregate: warp/dst, 1 lane/edge, linearity trick --
__global__ void k_agg1_csr(const float* __restrict__ x, const float* __restrict__ W1,
                           const float* __restrict__ b1, int n) {
    int warp = (blockIdx.x * blockDim.x + threadIdx.x) >> 5;
    if (warp >= n) return;
    int lane  = threadIdx.x & 31;
    int start = g_off[warp];
    int deg   = g_off[warp + 1] - start;
    float adv = g_ad[warp];
    float wa0 = g_w1a[0], wa1 = g_w1a[1];
    float psum = 0.f, px0 = 0.f, px1 = 0.f;
    for (int i = lane; i < deg; i += 32) {
        int src = g_srcl[start + i];
        float2 xv = ((const float2*)x)[src];
        float p = __expf(lrelu(xv.x * wa0 + xv.y * wa1 + adv));
        psum += p; px0 += p * xv.x; px1 += p * xv.y;
    }
    #pragma unroll
    for (int o = 16; o >= 1; o >>= 1) {       // post-loop: warp fully convergent
        psum += __shfl_xor_sync(FULL, psum, o);
        px0  += __shfl_xor_sync(FULL, px0,  o);
        px1  += __shfl_xor_sync(FULL, px1,  o);
    }
    if (lane < 16) {
        float sinv = 1.f / psum;
        float v = fmaxf((px0 * __ldg(W1 + lane) + px1 * __ldg(W1 + 16 + lane)) * sinv
                        + __ldg(b1 + lane), 0.f);
        g_out1[warp * 16 + lane] = v;
        float pd = v * g_w2a[16 + lane];      // alpha_dst for layer 2
        #pragma unroll
        for (int o = 8; o >= 1; o >>= 1)
            pd += __shfl_xor_sync(0xffffu, pd, o);
        if (lane == 0) g_ad[warp] = pd;
    }
}

// ---------------- layer2 aggregate: warp/dst, 4 lanes/edge, pipelined -------
__global__ void k_agg2_csr(const float* __restrict__ W2, const float* __restrict__ b2,
                           float* __restrict__ out, int n) {
    __shared__ float sW[1024];   // W2 16x64
    for (int i = threadIdx.x; i < 1024; i += blockDim.x) sW[i] = W2[i];
    __syncthreads();

    int warp = (blockIdx.x * blockDim.x + threadIdx.x) >> 5;
    if (warp >= n) return;
    int lane = threadIdx.x & 31;
    int fl   = lane & 3;             // feature slice (4 floats)
    int sub  = lane >> 2;            // 8 edges in parallel
    int start = g_off[warp];
    int deg   = g_off[warp + 1] - start;
    float adv = g_ad[warp];
    float wsa = g_w2a[fl * 4 + 0], wsb = g_w2a[fl * 4 + 1];
    float wsc = g_w2a[fl * 4 + 2], wsd = g_w2a[fl * 4 + 3];

    float4 acc = make_float4(0.f, 0.f, 0.f, 0.f);
    float psum = 0.f;
    int iters = (deg + 7) >> 3;                // warp-uniform trip count

    bool  v0 = (sub < deg);
    int   s0 = v0 ? g_srcl[start + sub] : 0;
    float4 hv0 = v0 ? *(const float4*)(g_out1 + s0 * 16 + fl * 4)
                    : make_float4(0.f, 0.f, 0.f, 0.f);

    for (int it = 0; it < iters; it++) {
        int i1 = (it + 1) * 8 + sub;
        bool v1 = (i1 < deg);
        int  s1 = v1 ? g_srcl[start + i1] : 0;
        float4 hv1 = v1 ? *(const float4*)(g_out1 + s1 * 16 + fl * 4)
                        : make_float4(0.f, 0.f, 0.f, 0.f);

        float pa = hv0.x * wsa + hv0.y * wsb + hv0.z * wsc + hv0.w * wsd;
        pa += __shfl_xor_sync(FULL, pa, 1);
        pa += __shfl_xor_sync(FULL, pa, 2);    // alpha_src, same in all 4 lanes
        float p = v0 ? __expf(lrelu(pa + adv)) : 0.f;
        psum += p;
        acc.x += p * hv0.x; acc.y += p * hv0.y;
        acc.z += p * hv0.z; acc.w += p * hv0.w;

        hv0 = hv1; v0 = v1;
    }
    #pragma unroll
    for (int o = 4; o <= 16; o <<= 1) {        // reduce across the 8 subgroups
        acc.x += __shfl_xor_sync(FULL, acc.x, o);
        acc.y += __shfl_xor_sync(FULL, acc.y, o);
        acc.z += __shfl_xor_sync(FULL, acc.z, o);
        acc.w += __shfl_xor_sync(FULL, acc.w, o);
        psum  += __shfl_xor_sync(FULL, psum,  o);
    }
    float sinv = 1.f / psum;
    float t[16];
    #pragma unroll
    for (int k = 0; k < 16; k++) {
        float c = ((k & 3) == 0) ? acc.x : ((k & 3) == 1) ? acc.y
                 : ((k & 3) == 2) ? acc.z : acc.w;
        t[k] = __shfl_sync(FULL, c, k >> 2) * sinv;   // lane (k>>2) has fl==k>>2
    }
    float2 r = make_float2(0.f, 0.f);
    #pragma unroll
    for (int k = 0; k < 16; k++) {
        float2 w = *(const float2*)&sW[k * 64 + 2 * lane];
        r.x += t[k] * w.x;
        r.y += t[k] * w.y;
    }
    float2 bb = __ldg((const float2*)b2 + lane);
    r.x = fmaxf(r.x + bb.x, 0.f);
    r.y = fmaxf(r.y + bb.y, 0.f);
    ((float2*)(out + warp * 64))[lane] = r;
}

// ---------------- launch -----------------------------------------------------
extern "C" void kernel_launch(void* const* d_in, const int* in_sizes, int n_in,
                              void* d_out, int out_size) {
    const float* x   = (const float*)d_in[0];
    const int*   ei  = (const int*)  d_in[1];
    const float* W1  = (const float*)d_in[2];
    const float* as1 = (const float*)d_in[3];
    const float* ad1 = (const float*)d_in[4];
    const float* b1  = (const float*)d_in[5];
    const float* W2  = (const float*)d_in[6];
    const float* as2 = (const float*)d_in[7];
    const float* ad2 = (const float*)d_in[8];
    const float* b2  = (const float*)d_in[9];
    float* out = (float*)d_out;

    int n  = in_sizes[0] / 2;   // 100000
    int E  = in_sizes[1] / 2;   // 3.2M
    int EE = E + n;

    const int T = 256;
    int E8c  = (E >> 3) + 1;                     // 8-edge threads (+tail thread)
    int hthr = E8c > n ? E8c : n;                // hist + node-init threads

    k_hist_init<<<(hthr + T - 1) / T, T>>>(ei, x, W1, as1, ad1, W2, as2, ad2, E, n);
    k_scan1<<<(n + SCAN_BLK - 1) / SCAN_BLK, SCAN_BLK>>>(n);
    k_scan23<<<(n + 255) / 256, 256>>>(n, EE);
    k_scatter<<<(E8c + T - 1) / T, T>>>(ei, E);
    k_agg1_csr<<<(n * 32 + T - 1) / T, T>>>(x, W1, b1, n);
    k_agg2_csr<<<(n * 32 + T - 1) / T, T>>>(W2, b2, out, n);
}